// round 1
// baseline (speedup 1.0000x reference)
#include <cuda_runtime.h>
#include <cuda_bf16.h>
#include <cstddef>

// Problem constants (registry shape): E=8, H=1024, I=2816, T=8192.
// T and E are derived from in_sizes at launch for robustness; H/I fixed.
#define HID 1024
#define INTER 2816
#define MAX_T 8192

// Scratch: o1/inter and o2. 92.3 MB each, static device globals (allowed).
__device__ float g_buf1[(size_t)MAX_T * INTER];
__device__ float g_buf2[(size_t)MAX_T * INTER];

// ---------------------------------------------------------------------------
// Grouped SGEMM: C[start+m0 .. ] = A[seg] * W[e], W[e] is K x N row-major.
// Block tile 128x128, BK=8, 256 threads, 8x8 per-thread microtile.
// grid = (ceil(T/128), N/128, E); blocks beyond the expert's segment exit.
// ---------------------------------------------------------------------------
#define BM 128
#define BN 128
#define BK 8
#define TM 8
#define TN 8

__global__ __launch_bounds__(256, 2)
void grouped_gemm_kernel(const float* __restrict__ A,
                         const float* __restrict__ W,
                         float* __restrict__ C,
                         const int* __restrict__ tokens_per_expert,
                         int K, int N)
{
    const int e = blockIdx.z;

    // Segment start for expert e (E is tiny; 8 cached loads).
    int start = 0;
    #pragma unroll 1
    for (int i = 0; i < e; ++i) start += tokens_per_expert[i];
    const int cnt = tokens_per_expert[e];

    const int m0 = blockIdx.x * BM;
    if (m0 >= cnt) return;                 // empty tile for this expert
    const int rows = min(BM, cnt - m0);

    const float* Ae = A + (size_t)(start + m0) * K;
    const float* We = W + (size_t)e * K * N;
    float*       Ce = C + (size_t)(start + m0) * N;
    const int n0 = blockIdx.y * BN;        // N is a multiple of BN here

    __shared__ float As[BK][BM];           // A stored transposed
    __shared__ float Bs[BK][BN];

    const int tid  = threadIdx.x;          // 0..255
    const int tcol = tid % (BN / TN);      // 0..15
    const int trow = tid / (BN / TN);      // 0..15

    float acc[TM][TN];
    #pragma unroll
    for (int i = 0; i < TM; ++i)
        #pragma unroll
        for (int j = 0; j < TN; ++j) acc[i][j] = 0.f;

    float ra[TM], rb[TN];

    for (int k0 = 0; k0 < K; k0 += BK) {
        // Load A tile: BM x BK (1024 elems, 4 per thread)
        #pragma unroll
        for (int i = 0; i < (BM * BK) / 256; ++i) {
            int idx = tid + i * 256;
            int r = idx / BK;
            int c = idx % BK;
            float v = (r < rows) ? Ae[(size_t)r * K + (k0 + c)] : 0.f;
            As[c][r] = v;
        }
        // Load B tile: BK x BN (1024 elems, 4 per thread), coalesced on N
        #pragma unroll
        for (int i = 0; i < (BK * BN) / 256; ++i) {
            int idx = tid + i * 256;
            int r = idx / BN;
            int c = idx % BN;
            Bs[r][c] = We[(size_t)(k0 + r) * N + (n0 + c)];
        }
        __syncthreads();

        #pragma unroll
        for (int kk = 0; kk < BK; ++kk) {
            #pragma unroll
            for (int i = 0; i < TM; ++i) ra[i] = As[kk][trow * TM + i];
            #pragma unroll
            for (int j = 0; j < TN; ++j) rb[j] = Bs[kk][tcol * TN + j];
            #pragma unroll
            for (int i = 0; i < TM; ++i)
                #pragma unroll
                for (int j = 0; j < TN; ++j)
                    acc[i][j] += ra[i] * rb[j];
        }
        __syncthreads();
    }

    // Store (vectorized: TN=8 -> two float4 per row)
    #pragma unroll
    for (int i = 0; i < TM; ++i) {
        int r = trow * TM + i;
        if (r < rows) {
            float4* dst = reinterpret_cast<float4*>(
                Ce + (size_t)r * N + n0 + tcol * TN);
            float4 v0 = make_float4(acc[i][0], acc[i][1], acc[i][2], acc[i][3]);
            float4 v1 = make_float4(acc[i][4], acc[i][5], acc[i][6], acc[i][7]);
            dst[0] = v0;
            dst[1] = v1;
        }
    }
}

// ---------------------------------------------------------------------------
// SwiGLU: buf1 <- silu(buf1) * buf2, float4 vectorized, grid-stride.
// ---------------------------------------------------------------------------
__global__ void swiglu_kernel(float* __restrict__ o1,
                              const float* __restrict__ o2,
                              size_t n4)
{
    size_t i = (size_t)blockIdx.x * blockDim.x + threadIdx.x;
    size_t stride = (size_t)gridDim.x * blockDim.x;
    float4* p1 = reinterpret_cast<float4*>(o1);
    const float4* p2 = reinterpret_cast<const float4*>(o2);
    for (; i < n4; i += stride) {
        float4 a = p1[i];
        float4 b = p2[i];
        a.x = a.x / (1.f + __expf(-a.x)) * b.x;
        a.y = a.y / (1.f + __expf(-a.y)) * b.y;
        a.z = a.z / (1.f + __expf(-a.z)) * b.z;
        a.w = a.w / (1.f + __expf(-a.w)) * b.w;
        p1[i] = a;
    }
}

// ---------------------------------------------------------------------------
// kernel_launch: gate-GEMM, up-GEMM, SwiGLU, down-GEMM. All graph-capturable.
// ---------------------------------------------------------------------------
extern "C" void kernel_launch(void* const* d_in, const int* in_sizes, int n_in,
                              void* d_out, int out_size)
{
    const float* x    = (const float*)d_in[0];   // [T, H]
    const float* gate = (const float*)d_in[1];   // [E, H, I]
    const float* up   = (const float*)d_in[2];   // [E, H, I]
    const float* down = (const float*)d_in[3];   // [E, I, H]
    const int*   tpe  = (const int*)d_in[4];     // [E]
    float* out = (float*)d_out;                  // [T, H]

    const int E = in_sizes[4];
    const int T = in_sizes[0] / HID;

    float *buf1, *buf2;
    cudaGetSymbolAddress((void**)&buf1, g_buf1);
    cudaGetSymbolAddress((void**)&buf2, g_buf2);

    const int mtiles = (T + BM - 1) / BM;
    dim3 blk(256);

    // GEMM 1a: o1 = x @ gate[e]   (K=H, N=I)
    dim3 g1(mtiles, INTER / BN, E);
    grouped_gemm_kernel<<<g1, blk>>>(x, gate, buf1, tpe, HID, INTER);

    // GEMM 1b: o2 = x @ up[e]
    grouped_gemm_kernel<<<g1, blk>>>(x, up, buf2, tpe, HID, INTER);

    // SwiGLU: buf1 = silu(buf1) * buf2
    size_t n4 = ((size_t)T * INTER) / 4;
    int sw_blocks = (int)((n4 + 255) / 256);
    if (sw_blocks > 8192) sw_blocks = 8192;
    swiglu_kernel<<<sw_blocks, 256>>>(buf1, buf2, n4);

    // GEMM 2: out = inter @ down[e]   (K=I, N=H)
    dim3 g2(mtiles, HID / BN, E);
    grouped_gemm_kernel<<<g2, blk>>>(buf1, down, out, tpe, INTER, HID);
}

// round 2
// speedup vs baseline: 1.0002x; 1.0002x over previous
#include <cuda_runtime.h>
#include <cuda_bf16.h>
#include <cstddef>

// Problem constants (registry shape): E=8, H=1024, I=2816, T=8192.
// T and E are derived from in_sizes at launch for robustness; H/I fixed.
#define HID 1024
#define INTER 2816
#define MAX_T 8192

// Scratch: o1/inter and o2. 92.3 MB each, static device globals (allowed).
__device__ float g_buf1[(size_t)MAX_T * INTER];
__device__ float g_buf2[(size_t)MAX_T * INTER];

// ---------------------------------------------------------------------------
// Grouped SGEMM: C[start+m0 .. ] = A[seg] * W[e], W[e] is K x N row-major.
// Block tile 128x128, BK=8, 256 threads, 8x8 per-thread microtile.
// grid = (ceil(T/128), N/128, E); blocks beyond the expert's segment exit.
// ---------------------------------------------------------------------------
#define BM 128
#define BN 128
#define BK 8
#define TM 8
#define TN 8

__global__ __launch_bounds__(256, 2)
void grouped_gemm_kernel(const float* __restrict__ A,
                         const float* __restrict__ W,
                         float* __restrict__ C,
                         const int* __restrict__ tokens_per_expert,
                         int K, int N)
{
    const int e = blockIdx.z;

    // Segment start for expert e (E is tiny; 8 cached loads).
    int start = 0;
    #pragma unroll 1
    for (int i = 0; i < e; ++i) start += tokens_per_expert[i];
    const int cnt = tokens_per_expert[e];

    const int m0 = blockIdx.x * BM;
    if (m0 >= cnt) return;                 // empty tile for this expert
    const int rows = min(BM, cnt - m0);

    const float* Ae = A + (size_t)(start + m0) * K;
    const float* We = W + (size_t)e * K * N;
    float*       Ce = C + (size_t)(start + m0) * N;
    const int n0 = blockIdx.y * BN;        // N is a multiple of BN here

    __shared__ float As[BK][BM];           // A stored transposed
    __shared__ float Bs[BK][BN];

    const int tid  = threadIdx.x;          // 0..255
    const int tcol = tid % (BN / TN);      // 0..15
    const int trow = tid / (BN / TN);      // 0..15

    float acc[TM][TN];
    #pragma unroll
    for (int i = 0; i < TM; ++i)
        #pragma unroll
        for (int j = 0; j < TN; ++j) acc[i][j] = 0.f;

    float ra[TM], rb[TN];

    for (int k0 = 0; k0 < K; k0 += BK) {
        // Load A tile: BM x BK (1024 elems, 4 per thread)
        #pragma unroll
        for (int i = 0; i < (BM * BK) / 256; ++i) {
            int idx = tid + i * 256;
            int r = idx / BK;
            int c = idx % BK;
            float v = (r < rows) ? Ae[(size_t)r * K + (k0 + c)] : 0.f;
            As[c][r] = v;
        }
        // Load B tile: BK x BN (1024 elems, 4 per thread), coalesced on N
        #pragma unroll
        for (int i = 0; i < (BK * BN) / 256; ++i) {
            int idx = tid + i * 256;
            int r = idx / BN;
            int c = idx % BN;
            Bs[r][c] = We[(size_t)(k0 + r) * N + (n0 + c)];
        }
        __syncthreads();

        #pragma unroll
        for (int kk = 0; kk < BK; ++kk) {
            #pragma unroll
            for (int i = 0; i < TM; ++i) ra[i] = As[kk][trow * TM + i];
            #pragma unroll
            for (int j = 0; j < TN; ++j) rb[j] = Bs[kk][tcol * TN + j];
            #pragma unroll
            for (int i = 0; i < TM; ++i)
                #pragma unroll
                for (int j = 0; j < TN; ++j)
                    acc[i][j] += ra[i] * rb[j];
        }
        __syncthreads();
    }

    // Store (vectorized: TN=8 -> two float4 per row)
    #pragma unroll
    for (int i = 0; i < TM; ++i) {
        int r = trow * TM + i;
        if (r < rows) {
            float4* dst = reinterpret_cast<float4*>(
                Ce + (size_t)r * N + n0 + tcol * TN);
            float4 v0 = make_float4(acc[i][0], acc[i][1], acc[i][2], acc[i][3]);
            float4 v1 = make_float4(acc[i][4], acc[i][5], acc[i][6], acc[i][7]);
            dst[0] = v0;
            dst[1] = v1;
        }
    }
}

// ---------------------------------------------------------------------------
// SwiGLU: buf1 <- silu(buf1) * buf2, float4 vectorized, grid-stride.
// ---------------------------------------------------------------------------
__global__ void swiglu_kernel(float* __restrict__ o1,
                              const float* __restrict__ o2,
                              size_t n4)
{
    size_t i = (size_t)blockIdx.x * blockDim.x + threadIdx.x;
    size_t stride = (size_t)gridDim.x * blockDim.x;
    float4* p1 = reinterpret_cast<float4*>(o1);
    const float4* p2 = reinterpret_cast<const float4*>(o2);
    for (; i < n4; i += stride) {
        float4 a = p1[i];
        float4 b = p2[i];
        a.x = a.x / (1.f + __expf(-a.x)) * b.x;
        a.y = a.y / (1.f + __expf(-a.y)) * b.y;
        a.z = a.z / (1.f + __expf(-a.z)) * b.z;
        a.w = a.w / (1.f + __expf(-a.w)) * b.w;
        p1[i] = a;
    }
}

// ---------------------------------------------------------------------------
// kernel_launch: gate-GEMM, up-GEMM, SwiGLU, down-GEMM. All graph-capturable.
// ---------------------------------------------------------------------------
extern "C" void kernel_launch(void* const* d_in, const int* in_sizes, int n_in,
                              void* d_out, int out_size)
{
    const float* x    = (const float*)d_in[0];   // [T, H]
    const float* gate = (const float*)d_in[1];   // [E, H, I]
    const float* up   = (const float*)d_in[2];   // [E, H, I]
    const float* down = (const float*)d_in[3];   // [E, I, H]
    const int*   tpe  = (const int*)d_in[4];     // [E]
    float* out = (float*)d_out;                  // [T, H]

    const int E = in_sizes[4];
    const int T = in_sizes[0] / HID;

    float *buf1, *buf2;
    cudaGetSymbolAddress((void**)&buf1, g_buf1);
    cudaGetSymbolAddress((void**)&buf2, g_buf2);

    const int mtiles = (T + BM - 1) / BM;
    dim3 blk(256);

    // GEMM 1a: o1 = x @ gate[e]   (K=H, N=I)
    dim3 g1(mtiles, INTER / BN, E);
    grouped_gemm_kernel<<<g1, blk>>>(x, gate, buf1, tpe, HID, INTER);

    // GEMM 1b: o2 = x @ up[e]
    grouped_gemm_kernel<<<g1, blk>>>(x, up, buf2, tpe, HID, INTER);

    // SwiGLU: buf1 = silu(buf1) * buf2
    size_t n4 = ((size_t)T * INTER) / 4;
    int sw_blocks = (int)((n4 + 255) / 256);
    if (sw_blocks > 8192) sw_blocks = 8192;
    swiglu_kernel<<<sw_blocks, 256>>>(buf1, buf2, n4);

    // GEMM 2: out = inter @ down[e]   (K=I, N=H)
    dim3 g2(mtiles, HID / BN, E);
    grouped_gemm_kernel<<<g2, blk>>>(buf1, down, out, tpe, INTER, HID);
}